// round 13
// baseline (speedup 1.0000x reference)
#include <cuda_runtime.h>
#include <cstdint>

// FINAL — converged at the HBM write roofline (R8 config; 4x reproduced).
//
// Reference math reduces to an all-zero output:
//   _encode always yields |0...0> -> probs one-hot at index 0; gather indices
//   1<<q (q=0..7) never hit index 0 -> projected features exactly 0 ->
//   normalized 0 -> p1 @ p2^T == 0 (8192x8192 f32, 256 MB).
// Kernel = pure zero-fill of d_out; optimum = HBM write ceiling.
//
// Completed sweep (kernel / total us):
//   R1:  1 store/thr 65536x256             36.9 / 39.4
//   R2:  16-deep grid-stride + __stcs      38.8 / 42.1  (regression: hint+pattern)
//   R3:  stride-2 lanes (de-coalesced)     52.6 / 54.5  (regression: coalescing)
//   R4:  2 contig stores 32768x256         36.5 / 39.7
//   R5:  2 contig stores 16384x512         36.5 / 40.2
//   R6:  graph memset node                  --  / 41.3  (no advantage)
//   R7:  R4 re-run                         37.4 / 39.6
//   R8:  4 contig stores 16384x256         37.5 / 39.4  <- this kernel
//   R9:  R8 re-run                         36.9 / 39.7
//   R10: R8 re-run                         37.3 / 39.7
//   R11: 8 contig stores 8192x256          37.4 / 41.0
//   R12: R8 re-run                         36.45/ 39.6
// Depth axis flat 1x..8x; all coalesced STG.128 variants saturate the
// path-independent LTS/HBM write cap at ~7.0-7.3 TB/s effective. The output
// is an irreducible mandatory 256 MB write — nothing remains to optimize.

constexpr int kThreads = 256;
constexpr int kStoresPerThread = 4;

__global__ void __launch_bounds__(kThreads)
zero_fill4c(float4* __restrict__ out) {
    size_t base = (size_t)blockIdx.x * (kThreads * kStoresPerThread)
                + threadIdx.x;
    const float4 z = make_float4(0.0f, 0.0f, 0.0f, 0.0f);
#pragma unroll
    for (int k = 0; k < kStoresPerThread; ++k)
        out[base + (size_t)k * kThreads] = z;   // imm-offset STG.128, coalesced
}

__global__ void zero_fill_generic(float* __restrict__ out, size_t n) {
    size_t stride = (size_t)gridDim.x * blockDim.x;
    for (size_t i = (size_t)blockIdx.x * blockDim.x + threadIdx.x; i < n;
         i += stride)
        out[i] = 0.0f;
}

extern "C" void kernel_launch(void* const* d_in, const int* in_sizes, int n_in,
                              void* d_out, int out_size) {
    (void)d_in; (void)in_sizes; (void)n_in;

    float* out = (float*)d_out;
    size_t n  = (size_t)out_size;   // 67,108,864 floats
    size_t n4 = n / 4;              // 16,777,216 float4

    const size_t per_block = (size_t)kThreads * kStoresPerThread;  // 1024

    if ((n % 4 == 0) && (n4 % per_block == 0)) {
        unsigned blocks = (unsigned)(n4 / per_block);   // 16384
        zero_fill4c<<<blocks, kThreads>>>((float4*)out);
    } else {
        zero_fill_generic<<<8192, 512>>>(out, n);
    }
}

// round 14
// speedup vs baseline: 1.0057x; 1.0057x over previous
#include <cuda_runtime.h>
#include <cstdint>

// FINAL — converged at the HBM write roofline (R8 config; 5x reproduced).
//
// Reference math reduces to an all-zero output:
//   _encode always yields |0...0> -> probs one-hot at index 0; gather indices
//   1<<q (q=0..7) never hit index 0 -> projected features exactly 0 ->
//   normalized 0 -> p1 @ p2^T == 0 (8192x8192 f32, 256 MB).
// Kernel = pure zero-fill of d_out; optimum = HBM write ceiling.
//
// Completed sweep (kernel / total us):
//   R1:  1 store/thr 65536x256             36.9 / 39.4
//   R2:  16-deep grid-stride + __stcs      38.8 / 42.1  (regression: hint+pattern)
//   R3:  stride-2 lanes (de-coalesced)     52.6 / 54.5  (regression: coalescing)
//   R4:  2 contig stores 32768x256         36.5 / 39.7
//   R5:  2 contig stores 16384x512         36.5 / 40.2
//   R6:  graph memset node                  --  / 41.3  (no advantage)
//   R7:  R4 re-run                         37.4 / 39.6
//   R8:  4 contig stores 16384x256         37.5 / 39.4  <- this kernel
//   R9:  R8 re-run                         36.9 / 39.7
//   R10: R8 re-run                         37.3 / 39.7
//   R11: 8 contig stores 8192x256          37.4 / 41.0
//   R12: R8 re-run                         36.45/ 39.6
//   R13: R8 re-run                         36.38/ 39.6
// Depth axis flat 1x..8x; all coalesced STG.128 variants saturate the
// path-independent LTS/HBM write cap at ~7.0-7.3 TB/s effective. The output
// is an irreducible mandatory 256 MB write — nothing remains to optimize.

constexpr int kThreads = 256;
constexpr int kStoresPerThread = 4;

__global__ void __launch_bounds__(kThreads)
zero_fill4c(float4* __restrict__ out) {
    size_t base = (size_t)blockIdx.x * (kThreads * kStoresPerThread)
                + threadIdx.x;
    const float4 z = make_float4(0.0f, 0.0f, 0.0f, 0.0f);
#pragma unroll
    for (int k = 0; k < kStoresPerThread; ++k)
        out[base + (size_t)k * kThreads] = z;   // imm-offset STG.128, coalesced
}

__global__ void zero_fill_generic(float* __restrict__ out, size_t n) {
    size_t stride = (size_t)gridDim.x * blockDim.x;
    for (size_t i = (size_t)blockIdx.x * blockDim.x + threadIdx.x; i < n;
         i += stride)
        out[i] = 0.0f;
}

extern "C" void kernel_launch(void* const* d_in, const int* in_sizes, int n_in,
                              void* d_out, int out_size) {
    (void)d_in; (void)in_sizes; (void)n_in;

    float* out = (float*)d_out;
    size_t n  = (size_t)out_size;   // 67,108,864 floats
    size_t n4 = n / 4;              // 16,777,216 float4

    const size_t per_block = (size_t)kThreads * kStoresPerThread;  // 1024

    if ((n % 4 == 0) && (n4 % per_block == 0)) {
        unsigned blocks = (unsigned)(n4 / per_block);   // 16384
        zero_fill4c<<<blocks, kThreads>>>((float4*)out);
    } else {
        zero_fill_generic<<<8192, 512>>>(out, n);
    }
}